// round 4
// baseline (speedup 1.0000x reference)
#include <cuda_runtime.h>
#include <math_constants.h>

#define B_  64
#define S_  4096
#define DX_ 512
#define Q_  128
#define DQ_ 512

// split geometry for attention: 8 blocks/batch, 16 warps/block
#define NB_      8
#define WPB_     16
#define WSPLITS_ (NB_ * WPB_)        // 128 warp-splits
#define RPW_     (S_ / WSPLITS_)     // 32 rows per warp

#define QS_ 4                        // q-splits for newq kernel

// scratch (static __device__ — allocation-free per harness rules)
__device__ __align__(16) float g_nq4[QS_ * B_ * DQ_];
__device__ __align__(16) float g_first[B_ * DX_];
__device__ float g_pm[B_ * NB_];
__device__ float g_pl[B_ * NB_];
__device__ __align__(16) float g_pctx[(size_t)B_ * NB_ * DX_];   // 1 MB
__device__ unsigned g_cnt[B_];       // zero-init; merging CTA resets to 0

// ---------------------------------------------------------------------------
// Kernel A: partial new_q over q-splits.
// grid (QS_, B_), block 256 (8 warps). Each warp: 4 contiguous qm rows,
// LDG.128, unroll 2 (8 float4 live -> no spills). smem reduce over 8 warps.
// ---------------------------------------------------------------------------
__global__ void __launch_bounds__(256) newq_kernel(
    const float* __restrict__ qm,   // [B, Q, DQ]
    const float* __restrict__ p)    // [Q]
{
    __shared__ float s_p[Q_ / QS_];
    __shared__ __align__(16) float s_acc[8][DQ_];        // 16 KB
    const int qs = blockIdx.x, b = blockIdx.y;
    const int t = threadIdx.x;
    const int w = t >> 5, lane = t & 31;
    const int q0 = qs * (Q_ / QS_);                      // 32 rows per CTA

    if (t < Q_ / QS_) s_p[t] = p[q0 + t];
    __syncthreads();

    float4 a0 = make_float4(0.f,0.f,0.f,0.f), a1 = a0, a2 = a0, a3 = a0;
    const float4* base = (const float4*)(qm + ((size_t)b * Q_ + q0) * DQ_);

    #pragma unroll 2
    for (int r = 0; r < 4; r++) {                        // 4 rows per warp
        const int q = w * 4 + r;
        const float4* row = base + (size_t)q * (DQ_ / 4);
        const float pq = s_p[q];
        const float4 r0 = row[lane], r1 = row[32+lane], r2 = row[64+lane], r3 = row[96+lane];
        a0.x += pq*r0.x; a0.y += pq*r0.y; a0.z += pq*r0.z; a0.w += pq*r0.w;
        a1.x += pq*r1.x; a1.y += pq*r1.y; a1.z += pq*r1.z; a1.w += pq*r1.w;
        a2.x += pq*r2.x; a2.y += pq*r2.y; a2.z += pq*r2.z; a2.w += pq*r2.w;
        a3.x += pq*r3.x; a3.y += pq*r3.y; a3.z += pq*r3.z; a3.w += pq*r3.w;
    }

    float4* sa = (float4*)s_acc[w];
    sa[lane] = a0; sa[32+lane] = a1; sa[64+lane] = a2; sa[96+lane] = a3;
    __syncthreads();

    // 256 threads reduce 512 columns (2 each)
    #pragma unroll
    for (int c = t; c < DQ_; c += 256) {
        float v = 0.f;
        #pragma unroll
        for (int i = 0; i < 8; i++) v += s_acc[i][c];
        g_nq4[((size_t)qs * B_ + b) * DQ_ + c] = v;
    }
}

// ---------------------------------------------------------------------------
// Kernel B: first[b,:] = new_q[b,:] @ W.
// grid (B_), block 256 (8 warps). Each warp: 64 contiguous W rows, LDG.128,
// unroll 2, acc = 4 float4 only. smem reduce over 8 warps.
// ---------------------------------------------------------------------------
__global__ void __launch_bounds__(256) first_kernel(
    const float* __restrict__ Wm)   // [DQ, DX]
{
    __shared__ float s_nq[DQ_];
    __shared__ __align__(16) float s_acc[8][DX_];        // 16 KB
    const int b = blockIdx.x;
    const int t = threadIdx.x;
    const int w = t >> 5, lane = t & 31;

    #pragma unroll
    for (int c = t; c < DQ_; c += 256) {
        float v = 0.f;
        #pragma unroll
        for (int qs = 0; qs < QS_; qs++)
            v += g_nq4[((size_t)qs * B_ + b) * DQ_ + c];
        s_nq[c] = v;
    }
    __syncthreads();

    float4 a0 = make_float4(0.f,0.f,0.f,0.f), a1 = a0, a2 = a0, a3 = a0;
    const float4* Wb = (const float4*)Wm;

    #pragma unroll 2
    for (int r = 0; r < DQ_ / 8; r++) {                  // 64 rows per warp
        const int d = w * (DQ_ / 8) + r;
        const float4* row = Wb + (size_t)d * (DX_ / 4);
        const float nd = s_nq[d];
        const float4 r0 = row[lane], r1 = row[32+lane], r2 = row[64+lane], r3 = row[96+lane];
        a0.x += nd*r0.x; a0.y += nd*r0.y; a0.z += nd*r0.z; a0.w += nd*r0.w;
        a1.x += nd*r1.x; a1.y += nd*r1.y; a1.z += nd*r1.z; a1.w += nd*r1.w;
        a2.x += nd*r2.x; a2.y += nd*r2.y; a2.z += nd*r2.z; a2.w += nd*r2.w;
        a3.x += nd*r3.x; a3.y += nd*r3.y; a3.z += nd*r3.z; a3.w += nd*r3.w;
    }

    float4* sa = (float4*)s_acc[w];
    sa[lane] = a0; sa[32+lane] = a1; sa[64+lane] = a2; sa[96+lane] = a3;
    __syncthreads();

    #pragma unroll
    for (int c = t; c < DX_; c += 256) {
        float v = 0.f;
        #pragma unroll
        for (int i = 0; i < 8; i++) v += s_acc[i][c];
        g_first[b * DX_ + c] = v;
    }
}

// ---------------------------------------------------------------------------
// Kernel 2: fused scores + online softmax + context partials + CTA reduce,
// with the cross-CTA merge fused via last-CTA-per-batch (threadfence pattern).
// x read exactly ONCE (streaming) -> DRAM-bound at 512MB.
// ---------------------------------------------------------------------------
__global__ void __launch_bounds__(512, 2) attn_partial_kernel(
    const float* __restrict__ x,    // [B, S, DX]
    float* __restrict__ out)        // [B, DX]
{
    const int b    = blockIdx.y;
    const int warp = threadIdx.x >> 5;
    const int lane = threadIdx.x & 31;
    const int t    = threadIdx.x;
    const int widx = blockIdx.x * WPB_ + warp;           // 0..127

    __shared__ __align__(16) float s_ctx[WPB_][DX_];     // 32 KB
    __shared__ float s_m[WPB_], s_l[WPB_];
    __shared__ int s_last;

    const float4* xb = (const float4*)(x + ((size_t)b * S_ + (size_t)widx * RPW_) * DX_);
    const float4* fp = (const float4*)(g_first + b * DX_);
    const float4 f0 = fp[lane], f1 = fp[32 + lane], f2 = fp[64 + lane], f3 = fp[96 + lane];

    float m = -CUDART_INF_F;
    float l = 0.f;
    float4 a0 = make_float4(0.f, 0.f, 0.f, 0.f), a1 = a0, a2 = a0, a3 = a0;

    #pragma unroll 1
    for (int r = 0; r < RPW_; r++) {
        const float4* xr = xb + (size_t)r * (DX_ / 4);
        const float4 x0 = __ldcs(xr + lane);
        const float4 x1 = __ldcs(xr + 32 + lane);
        const float4 x2 = __ldcs(xr + 64 + lane);
        const float4 x3 = __ldcs(xr + 96 + lane);

        float s = f0.x*x0.x + f0.y*x0.y + f0.z*x0.z + f0.w*x0.w
                + f1.x*x1.x + f1.y*x1.y + f1.z*x1.z + f1.w*x1.w
                + f2.x*x2.x + f2.y*x2.y + f2.z*x2.z + f2.w*x2.w
                + f3.x*x3.x + f3.y*x3.y + f3.z*x3.z + f3.w*x3.w;
        #pragma unroll
        for (int o = 16; o; o >>= 1)
            s += __shfl_xor_sync(0xffffffffu, s, o);     // all lanes hold score

        if (s <= m) {
            const float e = __expf(s - m);
            l += e;
            a0.x += e*x0.x; a0.y += e*x0.y; a0.z += e*x0.z; a0.w += e*x0.w;
            a1.x += e*x1.x; a1.y += e*x1.y; a1.z += e*x1.z; a1.w += e*x1.w;
            a2.x += e*x2.x; a2.y += e*x2.y; a2.z += e*x2.z; a2.w += e*x2.w;
            a3.x += e*x3.x; a3.y += e*x3.y; a3.z += e*x3.z; a3.w += e*x3.w;
        } else {
            const float c = __expf(m - s);               // exp(-inf)=0 on first row
            l = l * c + 1.f;
            m = s;
            a0.x = a0.x*c + x0.x; a0.y = a0.y*c + x0.y; a0.z = a0.z*c + x0.z; a0.w = a0.w*c + x0.w;
            a1.x = a1.x*c + x1.x; a1.y = a1.y*c + x1.y; a1.z = a1.z*c + x1.z; a1.w = a1.w*c + x1.w;
            a2.x = a2.x*c + x2.x; a2.y = a2.y*c + x2.y; a2.z = a2.z*c + x2.z; a2.w = a2.w*c + x2.w;
            a3.x = a3.x*c + x3.x; a3.y = a3.y*c + x3.y; a3.z = a3.z*c + x3.z; a3.w = a3.w*c + x3.w;
        }
    }

    // --- CTA-level reduce of 16 warp-partials (smem) ---
    {
        float4* row = (float4*)s_ctx[warp];
        row[lane] = a0; row[32 + lane] = a1; row[64 + lane] = a2; row[96 + lane] = a3;
        if (lane == 0) { s_m[warp] = m; s_l[warp] = l; }
    }
    __syncthreads();

    float M = -CUDART_INF_F;
    #pragma unroll
    for (int i = 0; i < WPB_; i++)
        M = fmaxf(M, s_m[i]);

    float L = 0.f, sum = 0.f;
    #pragma unroll
    for (int i = 0; i < WPB_; i++) {
        const float w = __expf(s_m[i] - M);
        L   += s_l[i] * w;
        sum += s_ctx[i][t] * w;
    }

    const int pi = b * NB_ + blockIdx.x;
    g_pctx[(size_t)pi * DX_ + t] = sum;
    if (t == 0) { g_pm[pi] = M; g_pl[pi] = L; }

    // --- fused cross-CTA merge: last CTA per batch finishes the job ---
    __threadfence();                 // make this CTA's partials GPU-visible
    __syncthreads();
    if (t == 0) {
        unsigned old = atomicAdd(&g_cnt[b], 1u);
        s_last = (old == NB_ - 1);
        if (s_last) g_cnt[b] = 0;    // reset for next graph replay
    }
    __syncthreads();

    if (s_last) {
        __threadfence();             // acquire: see all CTAs' partials

        float Mg = -CUDART_INF_F;
        #pragma unroll
        for (int i = 0; i < NB_; i++)
            Mg = fmaxf(Mg, g_pm[b * NB_ + i]);

        float Lg = 0.f, sg = 0.f;
        #pragma unroll
        for (int i = 0; i < NB_; i++) {
            const float w = __expf(g_pm[b * NB_ + i] - Mg);
            Lg += g_pl[b * NB_ + i] * w;
            sg += g_pctx[((size_t)b * NB_ + i) * DX_ + t] * w;
        }
        out[(size_t)b * DX_ + t] = sg / Lg;
    }
}

// ---------------------------------------------------------------------------
extern "C" void kernel_launch(void* const* d_in, const int* in_sizes, int n_in,
                              void* d_out, int out_size)
{
    const float* x  = nullptr;  // 64*4096*512 = 134217728
    const float* qm = nullptr;  // 64*128*512  = 4194304
    const float* Wm = nullptr;  // 512*512     = 262144
    const float* p  = nullptr;  // 128
    for (int i = 0; i < n_in; i++) {
        switch (in_sizes[i]) {
            case B_ * S_ * DX_: x  = (const float*)d_in[i]; break;
            case B_ * Q_ * DQ_: qm = (const float*)d_in[i]; break;
            case DQ_ * DX_:     Wm = (const float*)d_in[i]; break;
            case Q_:            p  = (const float*)d_in[i]; break;
            default: break;
        }
    }
    float* out = (float*)d_out;

    dim3 gA(QS_, B_);
    newq_kernel<<<gA, 256>>>(qm, p);
    first_kernel<<<B_, 256>>>(Wm);
    dim3 g2(NB_, B_);
    attn_partial_kernel<<<g2, 512>>>(x, out);
}